// round 16
// baseline (speedup 1.0000x reference)
#include <cuda_runtime.h>
#include <cuda_bf16.h>
#include <math.h>
#include <stdint.h>

#define Bsz 1024
#define INd 256
#define Hd  512
#define Pd  128

// ---------------- scratch (no allocations allowed) ----------------
__device__ float g_h0[Bsz * Hd];
__device__ float g_h1[Bsz * Hd];
__device__ float g_q [Bsz * Hd];
__device__ float g_k [Bsz * Hd];
__device__ float g_v [Bsz * Hd];

// bf16 hi/lo buffers: 10 weight segments + x
#define OFF_LIN0 0
#define OFF_B1Q  131072
#define OFF_B1K  393216
#define OFF_B1V  655360
#define OFF_B1F  917504
#define OFF_B2Q  1179648
#define OFF_B2K  1441792
#define OFF_B2V  1703936
#define OFF_B2F  1966080
#define OFF_FEA  2228224
#define OFF_X    2293760
#define WTOT     2555904
__device__ __nv_bfloat16 g_wh[WTOT];
__device__ __nv_bfloat16 g_wl[WTOT];
__device__ __nv_bfloat16 g_pAh[Bsz * Hd];
__device__ __nv_bfloat16 g_pAl[Bsz * Hd];
__device__ __nv_bfloat16 g_pBh[Bsz * Hd];
__device__ __nv_bfloat16 g_pBl[Bsz * Hd];

// ---------------- helpers ----------------
__device__ __forceinline__ float ex2f(float x) {
    float y; asm("ex2.approx.f32 %0, %1;" : "=f"(y) : "f"(x)); return y;
}
__device__ __forceinline__ float gelu_exact(float t) {
    return 0.5f * t * (1.0f + erff(t * 0.70710678118654752f));
}
__device__ __forceinline__ uint32_t smem_to_u32(const void* p) {
    uint32_t a;
    asm("{ .reg .u64 t; cvta.to.shared.u64 t, %1; cvt.u32.u64 %0, t; }" : "=r"(a) : "l"(p));
    return a;
}
#define CP16(dst, src) \
    asm volatile("cp.async.cg.shared.global [%0], [%1], 16;" :: "r"(dst), "l"(src))
#define CP_COMMIT() asm volatile("cp.async.commit_group;" ::: "memory")
#define CP_WAIT0()  asm volatile("cp.async.wait_group 0;" ::: "memory")

typedef unsigned long long u64t;

// packed f32x2 ops (exact per-lane fp32)
#define PACKAB(d, a, b) \
    asm("mov.b64 %0, {%1, %2};" : "=l"(d) : "f"(a), "f"(b))
#define UNPACK2(lo, hi, s) \
    asm("mov.b64 {%0, %1}, %2;" : "=f"(lo), "=f"(hi) : "l"(s))
#define UNPACKI(lo, hi, s) \
    asm("mov.b64 {%0, %1}, %2;" : "=r"(lo), "=r"(hi) : "l"(s))
#define PACKI(d, a, b) \
    asm("mov.b64 %0, {%1, %2};" : "=l"(d) : "r"(a), "r"(b))
#define FMA2N(d, a, b, c) \
    asm("fma.rn.f32x2 %0, %1, %2, %3;" : "=l"(d) : "l"(a), "l"(b), "l"(c))
#define FMA2(c, a, b) \
    asm("fma.rn.f32x2 %0, %1, %2, %0;" : "+l"(c) : "l"(a), "l"(b))
#define ADD2(c, a) \
    asm("add.rn.f32x2 %0, %1, %0;" : "+l"(c) : "l"(a))
#define ADD2N(d, a, b) \
    asm("add.rn.f32x2 %0, %1, %2;" : "=l"(d) : "l"(a), "l"(b))
#define MUL2N(d, a, b) \
    asm("mul.rn.f32x2 %0, %1, %2;" : "=l"(d) : "l"(a), "l"(b))

// mma.sync m16n8k16 bf16 (sm_80+ PTX, no arch-suffix gating)
__device__ __forceinline__ void mma16816(float c[4], const uint32_t a[4], const uint32_t b[2]) {
    asm volatile(
        "mma.sync.aligned.m16n8k16.row.col.f32.bf16.bf16.f32 "
        "{%0,%1,%2,%3}, {%4,%5,%6,%7}, {%8,%9}, {%0,%1,%2,%3};"
        : "+f"(c[0]), "+f"(c[1]), "+f"(c[2]), "+f"(c[3])
        : "r"(a[0]), "r"(a[1]), "r"(a[2]), "r"(a[3]), "r"(b[0]), "r"(b[1]));
}

// ---------------- conversion kernel: f32 -> (hi,lo) bf16 ----------------
#define NSEG 11
struct ConvArgs { const float* src[NSEG]; int off[NSEG]; int n4[NSEG]; };

__global__ __launch_bounds__(256) void conv_kernel(ConvArgs a) {
    const int s = blockIdx.y;
    const float* __restrict__ src = a.src[s];
    __nv_bfloat16* __restrict__ hi = g_wh + a.off[s];
    __nv_bfloat16* __restrict__ lo = g_wl + a.off[s];
    const int n4 = a.n4[s];
    for (int i = blockIdx.x * 256 + threadIdx.x; i < n4; i += gridDim.x * 256) {
        float4 v = ((const float4*)src)[i];
        __nv_bfloat16 h0 = __float2bfloat16(v.x), h1 = __float2bfloat16(v.y);
        __nv_bfloat16 h2 = __float2bfloat16(v.z), h3 = __float2bfloat16(v.w);
        ((__nv_bfloat162*)hi)[i * 2]     = __nv_bfloat162(h0, h1);
        ((__nv_bfloat162*)hi)[i * 2 + 1] = __nv_bfloat162(h2, h3);
        ((__nv_bfloat162*)lo)[i * 2] = __nv_bfloat162(
            __float2bfloat16(v.x - __bfloat162float(h0)),
            __float2bfloat16(v.y - __bfloat162float(h1)));
        ((__nv_bfloat162*)lo)[i * 2 + 1] = __nv_bfloat162(
            __float2bfloat16(v.z - __bfloat162float(h2)),
            __float2bfloat16(v.w - __bfloat162float(h3)));
    }
}

// ---------------- tensor GEMM (unchanged, proven in R11) ----------------
struct TGemmArgs {
    const __nv_bfloat16 *a_hi, *a_lo;
    const __nv_bfloat16 *w_hi[3], *w_lo[3];
    const float* bias[3];
    const float* res;
    float* C[3];
    __nv_bfloat16 *o_hi, *o_lo;
    int N;
};

#define ROWB 144
#define MATB (64 * ROWB)
#define SM_AH 0
#define SM_AL MATB
#define SM_WH (2 * MATB)
#define SM_WL (3 * MATB)

template <int EPI, int KD>
__global__ __launch_bounds__(128) void tgemm_kernel(TGemmArgs g) {
    __shared__ __align__(16) char smem[4 * MATB];
    const uint32_t sbase = smem_to_u32(smem);

    const int tid = threadIdx.x;
    const int wid = tid >> 5, lane = tid & 31;
    const int gid = lane >> 2, tig = lane & 3;
    const int warpRow = wid >> 1, warpCol = wid & 1;
    const int z = (EPI == 0) ? blockIdx.z : 0;
    const int n0 = blockIdx.x * 64;
    const int m0 = blockIdx.y * 64;
    const int N = g.N;
    const int Kb = KD * 2;

    const char* gA[2] = { (const char*)g.a_hi    + (size_t)m0 * Kb,
                          (const char*)g.a_lo    + (size_t)m0 * Kb };
    const char* gW[2] = { (const char*)g.w_hi[z] + (size_t)n0 * Kb,
                          (const char*)g.w_lo[z] + (size_t)n0 * Kb };

    float acc[2][4][4];
#pragma unroll
    for (int mt = 0; mt < 2; mt++)
#pragma unroll
        for (int nt = 0; nt < 4; nt++)
#pragma unroll
            for (int i = 0; i < 4; i++) acc[mt][nt][i] = 0.f;

    const int NCH = KD / 64;
    for (int c = 0; c < NCH; c++) {
#pragma unroll
        for (int mat = 0; mat < 4; mat++) {
            const char* gp = (mat < 2) ? gA[mat] : gW[mat - 2];
#pragma unroll
            for (int i = 0; i < 4; i++) {
                int u = tid + i * 128;
                int row = u >> 3, cb = (u & 7) * 16;
                CP16(sbase + mat * MATB + row * ROWB + cb,
                     gp + (size_t)row * Kb + c * 128 + cb);
            }
        }
        CP_COMMIT();
        CP_WAIT0();
        __syncthreads();

#pragma unroll
        for (int ks = 0; ks < 4; ks++) {
            const int kb = ks * 32;
            uint32_t ah[2][4], al[2][4], wh[4][2], wl[4][2];
#pragma unroll
            for (int mt = 0; mt < 2; mt++) {
                int ro = (warpRow * 32 + mt * 16 + gid) * ROWB + kb + tig * 4;
                ah[mt][0] = *(const uint32_t*)(smem + SM_AH + ro);
                ah[mt][1] = *(const uint32_t*)(smem + SM_AH + ro + 8 * ROWB);
                ah[mt][2] = *(const uint32_t*)(smem + SM_AH + ro + 16);
                ah[mt][3] = *(const uint32_t*)(smem + SM_AH + ro + 8 * ROWB + 16);
                al[mt][0] = *(const uint32_t*)(smem + SM_AL + ro);
                al[mt][1] = *(const uint32_t*)(smem + SM_AL + ro + 8 * ROWB);
                al[mt][2] = *(const uint32_t*)(smem + SM_AL + ro + 16);
                al[mt][3] = *(const uint32_t*)(smem + SM_AL + ro + 8 * ROWB + 16);
            }
#pragma unroll
            for (int nt = 0; nt < 4; nt++) {
                int ro = (warpCol * 32 + nt * 8 + gid) * ROWB + kb + tig * 4;
                wh[nt][0] = *(const uint32_t*)(smem + SM_WH + ro);
                wh[nt][1] = *(const uint32_t*)(smem + SM_WH + ro + 16);
                wl[nt][0] = *(const uint32_t*)(smem + SM_WL + ro);
                wl[nt][1] = *(const uint32_t*)(smem + SM_WL + ro + 16);
            }
#pragma unroll
            for (int mt = 0; mt < 2; mt++)
#pragma unroll
                for (int nt = 0; nt < 4; nt++) {
                    mma16816(acc[mt][nt], ah[mt], wh[nt]);
                    mma16816(acc[mt][nt], ah[mt], wl[nt]);
                    mma16816(acc[mt][nt], al[mt], wh[nt]);
                }
        }
        __syncthreads();
    }

    const float* __restrict__ bias = g.bias[z];
    float* __restrict__ C = g.C[z];
#pragma unroll
    for (int mt = 0; mt < 2; mt++) {
        const int gm0 = m0 + warpRow * 32 + mt * 16 + gid;
        const int gm1 = gm0 + 8;
#pragma unroll
        for (int nt = 0; nt < 4; nt++) {
            const int gn = n0 + warpCol * 32 + nt * 8 + tig * 2;
            const float b0 = bias[gn], b1 = bias[gn + 1];
            float v00 = acc[mt][nt][0] + b0, v01 = acc[mt][nt][1] + b1;
            float v10 = acc[mt][nt][2] + b0, v11 = acc[mt][nt][3] + b1;
            if (EPI == 2) {
                const int i0 = gm0 * N + gn, i1 = gm1 * N + gn;
                float2 r0 = *(const float2*)&g.res[i0];
                float2 r1 = *(const float2*)&g.res[i1];
                v00 = r0.x + gelu_exact(v00); v01 = r0.y + gelu_exact(v01);
                v10 = r1.x + gelu_exact(v10); v11 = r1.y + gelu_exact(v11);
            }
            *(float2*)&C[gm0 * N + gn] = make_float2(v00, v01);
            *(float2*)&C[gm1 * N + gn] = make_float2(v10, v11);
            if (EPI == 1 || EPI == 2) {
                __nv_bfloat16 h00 = __float2bfloat16(v00), h01 = __float2bfloat16(v01);
                __nv_bfloat16 h10 = __float2bfloat16(v10), h11 = __float2bfloat16(v11);
                *(__nv_bfloat162*)&g.o_hi[gm0 * N + gn] = __nv_bfloat162(h00, h01);
                *(__nv_bfloat162*)&g.o_hi[gm1 * N + gn] = __nv_bfloat162(h10, h11);
                *(__nv_bfloat162*)&g.o_lo[gm0 * N + gn] = __nv_bfloat162(
                    __float2bfloat16(v00 - __bfloat162float(h00)),
                    __float2bfloat16(v01 - __bfloat162float(h01)));
                *(__nv_bfloat162*)&g.o_lo[gm1 * N + gn] = __nv_bfloat162(
                    __float2bfloat16(v10 - __bfloat162float(h10)),
                    __float2bfloat16(v11 - __bfloat162float(h11)));
            }
        }
    }
}

// ---------------- attention: 256 thr / 2 rows, 3:1 MUFU/poly, DUAL acc chains ----------------
__global__ __launch_bounds__(256) void attn_kernel(const float* __restrict__ q,
                                                   const float* __restrict__ k,
                                                   const float* __restrict__ v,
                                                   float* __restrict__ h,
                                                   __nv_bfloat16* __restrict__ oh,
                                                   __nv_bfloat16* __restrict__ ol) {
    const int b = blockIdx.x;
    __shared__ float4 kv4[Hd];     // {kk, kk, vv, vv}
    __shared__ float red[256];
    const int tid = threadIdx.x;
    const float LOG2E = 1.4426950408889634f;

    float lmax = -1e30f, lmin = 1e30f;
#pragma unroll
    for (int ii = 0; ii < 2; ii++) {
        int j = tid + ii * 256;
        float kk = k[b * Hd + j] * LOG2E;
        float vv = v[b * Hd + j];
        kv4[j] = make_float4(kk, kk, vv, vv);
        lmax = fmaxf(lmax, kk);
        lmin = fminf(lmin, kk);
    }
    red[tid] = lmax; __syncthreads();
    for (int s = 128; s > 0; s >>= 1) {
        if (tid < s) red[tid] = fmaxf(red[tid], red[tid + s]);
        __syncthreads();
    }
    const float kmax = red[0];
    __syncthreads();
    red[tid] = lmin; __syncthreads();
    for (int s = 128; s > 0; s >>= 1) {
        if (tid < s) red[tid] = fminf(red[tid], red[tid + s]);
        __syncthreads();
    }
    const float kmin = red[0];

    const float q0 = q[b * Hd + tid];
    const float q1 = q[b * Hd + tid + 256];
    const float m0 = (q0 >= 0.f) ? q0 * kmax : q0 * kmin;   // max_j q*k (log2 domain)
    const float m1 = (q1 >= 0.f) ? q1 * kmax : q1 * kmin;

    u64t q01, nm01;
    PACKAB(q01, q0, q1);
    float nm0 = -m0, nm1 = -m1;
    PACKAB(nm01, nm0, nm1);

    // packed poly constants (exp2 minimax deg-4 on [-0.5, 0.5]); verified R14
    const float c4 = 9.61843735767464e-3f,  c3 = 5.550357105498875e-2f,
                c2 = 2.402264791865182e-1f, c1 = 6.931472028550421e-1f,
                c0 = 1.0f, MAGF = 12582912.0f, NMAGF = -12582912.0f, N1F = -1.0f;
    u64t C4, C3, C2, C1, C0, MAG2, NMAG2, NEG1;
    PACKAB(C4, c4, c4); PACKAB(C3, c3, c3); PACKAB(C2, c2, c2);
    PACKAB(C1, c1, c1); PACKAB(C0, c0, c0);
    PACKAB(MAG2, MAGF, MAGF); PACKAB(NMAG2, NMAGF, NMAGF); PACKAB(NEG1, N1F, N1F);

    // two independent accumulator chains (a: even groups, b: odd groups)
    u64t dA = 0ULL, nA = 0ULL, dB = 0ULL, nB = 0ULL;
    const ulonglong2* kvp = (const ulonglong2*)kv4;

#pragma unroll 2
    for (int j = 0; j < Hd; j += 8) {
        // ---- group A (j..j+3): 3 MUFU + 1 poly -> dA/nA ----
        // ---- group B (j+4..j+7): 3 MUFU + 1 poly -> dB/nB ----
#pragma unroll
        for (int grp = 0; grp < 2; grp++) {
            const int base = j + grp * 4;
#pragma unroll
            for (int s = 0; s < 3; s++) {
                ulonglong2 kvv = kvp[base + s];     // one LDS.128: {kk,kk | vv,vv}
                u64t t01;
                FMA2N(t01, q01, kvv.x, nm01);
                float t0, t1;
                UNPACK2(t0, t1, t01);
                float e0 = ex2f(t0), e1 = ex2f(t1);
                u64t e01;
                PACKAB(e01, e0, e1);
                if (grp == 0) { ADD2(dA, e01); FMA2(nA, e01, kvv.y); }
                else          { ADD2(dB, e01); FMA2(nB, e01, kvv.y); }
            }
            {
                ulonglong2 kvv = kvp[base + 3];
                u64t t01;
                FMA2N(t01, q01, kvv.x, nm01);
                u64t fm01;
                ADD2N(fm01, t01, MAG2);          // fm = MAG + round(t), bits carry n
                u64t nI01, f01, tmp;
                ADD2N(nI01, fm01, NMAG2);        // n (exact, Sterbenz)
                FMA2N(f01, nI01, NEG1, t01);     // f = t - n (exact, |f| <= 0.5)
                u64t p01;
                FMA2N(p01, f01, C4, C3);
                FMA2N(tmp, p01, f01, C2); p01 = tmp;
                FMA2N(tmp, p01, f01, C1); p01 = tmp;
                FMA2N(tmp, p01, f01, C0); p01 = tmp;
                uint32_t u0, u1;
                UNPACKI(u0, u1, fm01);
                int s0 = (int)((u0 << 23) + 0x3F800000u); s0 = max(s0, 0);
                int s1 = (int)((u1 << 23) + 0x3F800000u); s1 = max(s1, 0);
                u64t sc01;
                PACKI(sc01, (uint32_t)s0, (uint32_t)s1);
                u64t e01;
                MUL2N(e01, p01, sc01);
                if (grp == 0) { ADD2(dA, e01); FMA2(nA, e01, kvv.y); }
                else          { ADD2(dB, e01); FMA2(nB, e01, kvv.y); }
            }
        }
    }

    u64t d01, n01;
    ADD2N(d01, dA, dB);
    ADD2N(n01, nA, nB);

    float D0, D1, N0, N1;
    UNPACK2(D0, D1, d01);
    UNPACK2(N0, N1, n01);
    int i0 = b * Hd + tid, i1 = i0 + 256;
    float r0 = h[i0] + N0 / D0;
    float r1 = h[i1] + N1 / D1;
    h[i0] = r0; h[i1] = r1;
    __nv_bfloat16 h0b = __float2bfloat16(r0);
    __nv_bfloat16 h1b = __float2bfloat16(r1);
    oh[i0] = h0b; ol[i0] = __float2bfloat16(r0 - __bfloat162float(h0b));
    oh[i1] = h1b; ol[i1] = __float2bfloat16(r1 - __bfloat162float(h1b));
}

// ---------------- reg head ----------------
__global__ __launch_bounds__(256) void reg_kernel(const float* __restrict__ fea,
                                                  const float* __restrict__ reg_w,
                                                  const float* __restrict__ reg_b,
                                                  float* __restrict__ out) {
    const int warp = (blockIdx.x * blockDim.x + threadIdx.x) >> 5;
    const int lane = threadIdx.x & 31;
    if (warp >= Bsz) return;
    float s = 0.f;
#pragma unroll
    for (int p = lane; p < Pd; p += 32)
        s = fmaf(fea[warp * Pd + p], reg_w[p], s);
#pragma unroll
    for (int o = 16; o; o >>= 1) s += __shfl_xor_sync(0xffffffffu, s, o);
    if (lane == 0) out[warp] = s + reg_b[0];
}

// ---------------- launcher (single stream, R11 structure) ----------------
extern "C" void kernel_launch(void* const* d_in, const int* in_sizes, int n_in,
                              void* d_out, int out_size) {
    const float* x      = (const float*)d_in[0];
    const float* lin0_w = (const float*)d_in[1];
    const float* lin0_b = (const float*)d_in[2];
    const float* b1_qw = (const float*)d_in[3];  const float* b1_qb = (const float*)d_in[4];
    const float* b1_kw = (const float*)d_in[5];  const float* b1_kb = (const float*)d_in[6];
    const float* b1_vw = (const float*)d_in[7];  const float* b1_vb = (const float*)d_in[8];
    const float* b1_f1w = (const float*)d_in[9]; const float* b1_f1b = (const float*)d_in[10];
    const float* b2_qw = (const float*)d_in[11]; const float* b2_qb = (const float*)d_in[12];
    const float* b2_kw = (const float*)d_in[13]; const float* b2_kb = (const float*)d_in[14];
    const float* b2_vw = (const float*)d_in[15]; const float* b2_vb = (const float*)d_in[16];
    const float* b2_f1w = (const float*)d_in[17]; const float* b2_f1b = (const float*)d_in[18];
    const float* fea_w = (const float*)d_in[19]; const float* fea_b = (const float*)d_in[20];
    const float* reg_w = (const float*)d_in[21]; const float* reg_b = (const float*)d_in[22];

    float* out_scalar = (float*)d_out;           // [B]
    float* out_fea    = (float*)d_out + Bsz;     // [B, P]

    float *h0, *h1, *qb, *kb, *vb;
    __nv_bfloat16 *wh, *wl, *pAh, *pAl, *pBh, *pBl;
    cudaGetSymbolAddress((void**)&h0, g_h0);
    cudaGetSymbolAddress((void**)&h1, g_h1);
    cudaGetSymbolAddress((void**)&qb, g_q);
    cudaGetSymbolAddress((void**)&kb, g_k);
    cudaGetSymbolAddress((void**)&vb, g_v);
    cudaGetSymbolAddress((void**)&wh, g_wh);
    cudaGetSymbolAddress((void**)&wl, g_wl);
    cudaGetSymbolAddress((void**)&pAh, g_pAh);
    cudaGetSymbolAddress((void**)&pAl, g_pAl);
    cudaGetSymbolAddress((void**)&pBh, g_pBh);
    cudaGetSymbolAddress((void**)&pBl, g_pBl);

    // 0) convert all weights + x to bf16 hi/lo
    {
        ConvArgs a{};
        const float* srcs[NSEG] = {lin0_w, b1_qw, b1_kw, b1_vw, b1_f1w,
                                   b2_qw, b2_kw, b2_vw, b2_f1w, fea_w, x};
        const int offs[NSEG] = {OFF_LIN0, OFF_B1Q, OFF_B1K, OFF_B1V, OFF_B1F,
                                OFF_B2Q, OFF_B2K, OFF_B2V, OFF_B2F, OFF_FEA, OFF_X};
        const int ns[NSEG] = {Hd*INd, Hd*Hd, Hd*Hd, Hd*Hd, Hd*Hd,
                              Hd*Hd, Hd*Hd, Hd*Hd, Hd*Hd, Pd*Hd, Bsz*INd};
        for (int s = 0; s < NSEG; s++) { a.src[s] = srcs[s]; a.off[s] = offs[s]; a.n4[s] = ns[s] / 4; }
        conv_kernel<<<dim3(48, NSEG), 256>>>(a);
    }

    // 1) lin0: h0 = x @ lin0_w^T + b  (+ bf16 pair A)
    {
        TGemmArgs a{};
        a.a_hi = wh + OFF_X; a.a_lo = wl + OFF_X;
        a.w_hi[0] = wh + OFF_LIN0; a.w_lo[0] = wl + OFF_LIN0;
        a.bias[0] = lin0_b; a.C[0] = h0;
        a.o_hi = pAh; a.o_lo = pAl; a.N = Hd;
        tgemm_kernel<1, 256><<<dim3(8, 16, 1), 128>>>(a);
    }

    // ---- block 1 ----
    {
        TGemmArgs a{};
        a.a_hi = pAh; a.a_lo = pAl;
        a.w_hi[0] = wh + OFF_B1Q; a.w_lo[0] = wl + OFF_B1Q;
        a.w_hi[1] = wh + OFF_B1K; a.w_lo[1] = wl + OFF_B1K;
        a.w_hi[2] = wh + OFF_B1V; a.w_lo[2] = wl + OFF_B1V;
        a.bias[0] = b1_qb; a.bias[1] = b1_kb; a.bias[2] = b1_vb;
        a.C[0] = qb; a.C[1] = kb; a.C[2] = vb; a.N = Hd;
        tgemm_kernel<0, 512><<<dim3(8, 16, 3), 128>>>(a);
    }
    attn_kernel<<<Bsz, 256>>>(qb, kb, vb, h0, pAh, pAl);
    {
        TGemmArgs a{};
        a.a_hi = pAh; a.a_lo = pAl;
        a.w_hi[0] = wh + OFF_B1F; a.w_lo[0] = wl + OFF_B1F;
        a.bias[0] = b1_f1b; a.res = h0; a.C[0] = h1;
        a.o_hi = pBh; a.o_lo = pBl; a.N = Hd;
        tgemm_kernel<2, 512><<<dim3(8, 16, 1), 128>>>(a);
    }

    // ---- block 2 ----
    {
        TGemmArgs a{};
        a.a_hi = pBh; a.a_lo = pBl;
        a.w_hi[0] = wh + OFF_B2Q; a.w_lo[0] = wl + OFF_B2Q;
        a.w_hi[1] = wh + OFF_B2K; a.w_lo[1] = wl + OFF_B2K;
        a.w_hi[2] = wh + OFF_B2V; a.w_lo[2] = wl + OFF_B2V;
        a.bias[0] = b2_qb; a.bias[1] = b2_kb; a.bias[2] = b2_vb;
        a.C[0] = qb; a.C[1] = kb; a.C[2] = vb; a.N = Hd;
        tgemm_kernel<0, 512><<<dim3(8, 16, 3), 128>>>(a);
    }
    attn_kernel<<<Bsz, 256>>>(qb, kb, vb, h1, pBh, pBl);
    {
        TGemmArgs a{};
        a.a_hi = pBh; a.a_lo = pBl;
        a.w_hi[0] = wh + OFF_B2F; a.w_lo[0] = wl + OFF_B2F;
        a.bias[0] = b2_f1b; a.res = h1; a.C[0] = h0;
        a.o_hi = pAh; a.o_lo = pAl; a.N = Hd;
        tgemm_kernel<2, 512><<<dim3(8, 16, 1), 128>>>(a);
    }

    // 4) fea -> d_out directly
    {
        TGemmArgs a{};
        a.a_hi = pAh; a.a_lo = pAl;
        a.w_hi[0] = wh + OFF_FEA; a.w_lo[0] = wl + OFF_FEA;
        a.bias[0] = fea_b; a.C[0] = out_fea; a.N = Pd;
        tgemm_kernel<3, 512><<<dim3(2, 16, 1), 128>>>(a);
    }

    // 5) out[b] = fea·reg_w + reg_b
    reg_kernel<<<(Bsz * 32) / 256, 256>>>(out_fea, reg_w, reg_b, out_scalar);
}

// round 17
// speedup vs baseline: 1.1700x; 1.1700x over previous
#include <cuda_runtime.h>
#include <cuda_bf16.h>
#include <math.h>
#include <stdint.h>

#define Bsz 1024
#define INd 256
#define Hd  512
#define Pd  128

// ---------------- scratch (no allocations allowed) ----------------
__device__ float g_h0[Bsz * Hd];
__device__ float g_h1[Bsz * Hd];
__device__ float g_q [Bsz * Hd];
__device__ float g_k [Bsz * Hd];
__device__ float g_v [Bsz * Hd];

// bf16 hi/lo buffers: 10 weight segments + x
#define OFF_LIN0 0
#define OFF_B1Q  131072
#define OFF_B1K  393216
#define OFF_B1V  655360
#define OFF_B1F  917504
#define OFF_B2Q  1179648
#define OFF_B2K  1441792
#define OFF_B2V  1703936
#define OFF_B2F  1966080
#define OFF_FEA  2228224
#define OFF_X    2293760
#define WTOT     2555904
__device__ __nv_bfloat16 g_wh[WTOT];
__device__ __nv_bfloat16 g_wl[WTOT];
__device__ __nv_bfloat16 g_pAh[Bsz * Hd];
__device__ __nv_bfloat16 g_pAl[Bsz * Hd];
__device__ __nv_bfloat16 g_pBh[Bsz * Hd];
__device__ __nv_bfloat16 g_pBl[Bsz * Hd];

// ---------------- helpers ----------------
__device__ __forceinline__ float ex2f(float x) {
    float y; asm("ex2.approx.f32 %0, %1;" : "=f"(y) : "f"(x)); return y;
}
__device__ __forceinline__ float gelu_exact(float t) {
    return 0.5f * t * (1.0f + erff(t * 0.70710678118654752f));
}
__device__ __forceinline__ uint32_t smem_to_u32(const void* p) {
    uint32_t a;
    asm("{ .reg .u64 t; cvta.to.shared.u64 t, %1; cvt.u32.u64 %0, t; }" : "=r"(a) : "l"(p));
    return a;
}
#define CP16(dst, src) \
    asm volatile("cp.async.cg.shared.global [%0], [%1], 16;" :: "r"(dst), "l"(src))
#define CP_COMMIT() asm volatile("cp.async.commit_group;" ::: "memory")
#define CP_WAIT0()  asm volatile("cp.async.wait_group 0;" ::: "memory")
#define CP_WAIT1()  asm volatile("cp.async.wait_group 1;" ::: "memory")

// mma.sync m16n8k16 bf16 (sm_80+ PTX, no arch-suffix gating)
__device__ __forceinline__ void mma16816(float c[4], const uint32_t a[4], const uint32_t b[2]) {
    asm volatile(
        "mma.sync.aligned.m16n8k16.row.col.f32.bf16.bf16.f32 "
        "{%0,%1,%2,%3}, {%4,%5,%6,%7}, {%8,%9}, {%0,%1,%2,%3};"
        : "+f"(c[0]), "+f"(c[1]), "+f"(c[2]), "+f"(c[3])
        : "r"(a[0]), "r"(a[1]), "r"(a[2]), "r"(a[3]), "r"(b[0]), "r"(b[1]));
}

// ---------------- conversion kernel: f32 -> (hi,lo) bf16 ----------------
#define NSEG 11
struct ConvArgs { const float* src[NSEG]; int off[NSEG]; int n4[NSEG]; };

__global__ __launch_bounds__(256) void conv_kernel(ConvArgs a) {
    const int s = blockIdx.y;
    const float* __restrict__ src = a.src[s];
    __nv_bfloat16* __restrict__ hi = g_wh + a.off[s];
    __nv_bfloat16* __restrict__ lo = g_wl + a.off[s];
    const int n4 = a.n4[s];
    for (int i = blockIdx.x * 256 + threadIdx.x; i < n4; i += gridDim.x * 256) {
        float4 v = ((const float4*)src)[i];
        __nv_bfloat16 h0 = __float2bfloat16(v.x), h1 = __float2bfloat16(v.y);
        __nv_bfloat16 h2 = __float2bfloat16(v.z), h3 = __float2bfloat16(v.w);
        ((__nv_bfloat162*)hi)[i * 2]     = __nv_bfloat162(h0, h1);
        ((__nv_bfloat162*)hi)[i * 2 + 1] = __nv_bfloat162(h2, h3);
        ((__nv_bfloat162*)lo)[i * 2] = __nv_bfloat162(
            __float2bfloat16(v.x - __bfloat162float(h0)),
            __float2bfloat16(v.y - __bfloat162float(h1)));
        ((__nv_bfloat162*)lo)[i * 2 + 1] = __nv_bfloat162(
            __float2bfloat16(v.z - __bfloat162float(h2)),
            __float2bfloat16(v.w - __bfloat162float(h3)));
    }
}

// ---------------- tensor GEMM: double-buffered cp.async pipeline ----------------
struct TGemmArgs {
    const __nv_bfloat16 *a_hi, *a_lo;
    const __nv_bfloat16 *w_hi[3], *w_lo[3];
    const float* bias[3];
    const float* res;
    float* C[3];
    __nv_bfloat16 *o_hi, *o_lo;
    int N;
};

#define ROWB 144
#define MATB (64 * ROWB)
#define SM_AH 0
#define SM_AL MATB
#define SM_WH (2 * MATB)
#define SM_WL (3 * MATB)
#define STAGEB (4 * MATB)          // one pipeline stage = 36,864 B
#define SMEM_DBL (2 * STAGEB)      // 73,728 B dynamic

template <int EPI, int KD>
__global__ __launch_bounds__(128) void tgemm_kernel(TGemmArgs g) {
    extern __shared__ __align__(16) char smem[];
    const uint32_t sbase = smem_to_u32(smem);

    const int tid = threadIdx.x;
    const int wid = tid >> 5, lane = tid & 31;
    const int gid = lane >> 2, tig = lane & 3;
    const int warpRow = wid >> 1, warpCol = wid & 1;
    const int z = (EPI == 0) ? blockIdx.z : 0;
    const int n0 = blockIdx.x * 64;
    const int m0 = blockIdx.y * 64;
    const int N = g.N;
    const int Kb = KD * 2;

    const char* gA[2] = { (const char*)g.a_hi    + (size_t)m0 * Kb,
                          (const char*)g.a_lo    + (size_t)m0 * Kb };
    const char* gW[2] = { (const char*)g.w_hi[z] + (size_t)n0 * Kb,
                          (const char*)g.w_lo[z] + (size_t)n0 * Kb };

    // stage loader: chunk cc -> smem stage at byte offset bo
    auto stage = [&](int cc, int bo) {
#pragma unroll
        for (int mat = 0; mat < 4; mat++) {
            const char* gp = (mat < 2) ? gA[mat] : gW[mat - 2];
#pragma unroll
            for (int i = 0; i < 4; i++) {
                int u = tid + i * 128;
                int row = u >> 3, cb = (u & 7) * 16;
                CP16(sbase + bo + mat * MATB + row * ROWB + cb,
                     gp + (size_t)row * Kb + cc * 128 + cb);
            }
        }
    };

    float acc[2][4][4];
#pragma unroll
    for (int mt = 0; mt < 2; mt++)
#pragma unroll
        for (int nt = 0; nt < 4; nt++)
#pragma unroll
            for (int i = 0; i < 4; i++) acc[mt][nt][i] = 0.f;

    const int NCH = KD / 64;
    stage(0, 0);
    CP_COMMIT();

    for (int c = 0; c < NCH; c++) {
        const int bo = (c & 1) * STAGEB;
        if (c + 1 < NCH) {             // prefetch next chunk into other stage
            stage(c + 1, (bo == 0) ? STAGEB : 0);
            CP_COMMIT();
            CP_WAIT1();                // chunk c complete; c+1 may be in flight
        } else {
            CP_WAIT0();
        }
        __syncthreads();

#pragma unroll
        for (int ks = 0; ks < 4; ks++) {
            const int kb = ks * 32;
            uint32_t ah[2][4], al[2][4], wh[4][2], wl[4][2];
#pragma unroll
            for (int mt = 0; mt < 2; mt++) {
                int ro = bo + (warpRow * 32 + mt * 16 + gid) * ROWB + kb + tig * 4;
                ah[mt][0] = *(const uint32_t*)(smem + SM_AH + ro);
                ah[mt][1] = *(const uint32_t*)(smem + SM_AH + ro + 8 * ROWB);
                ah[mt][2] = *(const uint32_t*)(smem + SM_AH + ro + 16);
                ah[mt][3] = *(const uint32_t*)(smem + SM_AH + ro + 8 * ROWB + 16);
                al[mt][0] = *(const uint32_t*)(smem + SM_AL + ro);
                al[mt][1] = *(const uint32_t*)(smem + SM_AL + ro + 8 * ROWB);
                al[mt][2] = *(const uint32_t*)(smem + SM_AL + ro + 16);
                al[mt][3] = *(const uint32_t*)(smem + SM_AL + ro + 8 * ROWB + 16);
            }
#pragma unroll
            for (int nt = 0; nt < 4; nt++) {
                int ro = bo + (warpCol * 32 + nt * 8 + gid) * ROWB + kb + tig * 4;
                wh[nt][0] = *(const uint32_t*)(smem + SM_WH + ro);
                wh[nt][1] = *(const uint32_t*)(smem + SM_WH + ro + 16);
                wl[nt][0] = *(const uint32_t*)(smem + SM_WL + ro);
                wl[nt][1] = *(const uint32_t*)(smem + SM_WL + ro + 16);
            }
#pragma unroll
            for (int mt = 0; mt < 2; mt++)
#pragma unroll
                for (int nt = 0; nt < 4; nt++) {
                    mma16816(acc[mt][nt], ah[mt], wh[nt]);
                    mma16816(acc[mt][nt], ah[mt], wl[nt]);
                    mma16816(acc[mt][nt], al[mt], wh[nt]);
                }
        }
        __syncthreads();   // stage compute done before its buffer is re-staged
    }

    const float* __restrict__ bias = g.bias[z];
    float* __restrict__ C = g.C[z];
#pragma unroll
    for (int mt = 0; mt < 2; mt++) {
        const int gm0 = m0 + warpRow * 32 + mt * 16 + gid;
        const int gm1 = gm0 + 8;
#pragma unroll
        for (int nt = 0; nt < 4; nt++) {
            const int gn = n0 + warpCol * 32 + nt * 8 + tig * 2;
            const float b0 = bias[gn], b1 = bias[gn + 1];
            float v00 = acc[mt][nt][0] + b0, v01 = acc[mt][nt][1] + b1;
            float v10 = acc[mt][nt][2] + b0, v11 = acc[mt][nt][3] + b1;
            if (EPI == 2) {
                const int i0 = gm0 * N + gn, i1 = gm1 * N + gn;
                float2 r0 = *(const float2*)&g.res[i0];
                float2 r1 = *(const float2*)&g.res[i1];
                v00 = r0.x + gelu_exact(v00); v01 = r0.y + gelu_exact(v01);
                v10 = r1.x + gelu_exact(v10); v11 = r1.y + gelu_exact(v11);
            }
            *(float2*)&C[gm0 * N + gn] = make_float2(v00, v01);
            *(float2*)&C[gm1 * N + gn] = make_float2(v10, v11);
            if (EPI == 1 || EPI == 2) {
                __nv_bfloat16 h00 = __float2bfloat16(v00), h01 = __float2bfloat16(v01);
                __nv_bfloat16 h10 = __float2bfloat16(v10), h11 = __float2bfloat16(v11);
                *(__nv_bfloat162*)&g.o_hi[gm0 * N + gn] = __nv_bfloat162(h00, h01);
                *(__nv_bfloat162*)&g.o_hi[gm1 * N + gn] = __nv_bfloat162(h10, h11);
                *(__nv_bfloat162*)&g.o_lo[gm0 * N + gn] = __nv_bfloat162(
                    __float2bfloat16(v00 - __bfloat162float(h00)),
                    __float2bfloat16(v01 - __bfloat162float(h01)));
                *(__nv_bfloat162*)&g.o_lo[gm1 * N + gn] = __nv_bfloat162(
                    __float2bfloat16(v10 - __bfloat162float(h10)),
                    __float2bfloat16(v11 - __bfloat162float(h11)));
            }
        }
    }
}

// ---------------- attention: R11 verbatim (proven 61.9us, MUFU floor) ----------------
__global__ __launch_bounds__(256) void attn_kernel(const float* __restrict__ q,
                                                   const float* __restrict__ k,
                                                   const float* __restrict__ v,
                                                   float* __restrict__ h,
                                                   __nv_bfloat16* __restrict__ oh,
                                                   __nv_bfloat16* __restrict__ ol) {
    const int b = blockIdx.x;
    __shared__ float k2s[Hd];
    __shared__ float vs[Hd];
    __shared__ float redmax[256];
    __shared__ float redmin[256];
    const int tid = threadIdx.x;
    const float LOG2E = 1.4426950408889634f;

    float lmax = -1e30f, lmin = 1e30f;
#pragma unroll
    for (int ii = 0; ii < Hd / 256; ii++) {
        int j = tid + ii * 256;
        float kk = k[b * Hd + j] * LOG2E;
        k2s[j] = kk;
        vs[j]  = v[b * Hd + j];
        lmax = fmaxf(lmax, kk);
        lmin = fminf(lmin, kk);
    }
    redmax[tid] = lmax;
    redmin[tid] = lmin;
    __syncthreads();
    for (int s = 128; s > 0; s >>= 1) {
        if (tid < s) {
            redmax[tid] = fmaxf(redmax[tid], redmax[tid + s]);
            redmin[tid] = fminf(redmin[tid], redmin[tid + s]);
        }
        __syncthreads();
    }
    const float kmax = redmax[0], kmin = redmin[0];

    const float q0 = q[b * Hd + tid];
    const float q1 = q[b * Hd + tid + 256];
    const float m0 = (q0 >= 0.f) ? q0 * kmax : q0 * kmin;
    const float m1 = (q1 >= 0.f) ? q1 * kmax : q1 * kmin;

    float d0 = 0.f, d1 = 0.f, n0 = 0.f, n1 = 0.f;
#pragma unroll 8
    for (int j = 0; j < Hd; j++) {
        float kv = k2s[j];
        float vv = vs[j];
        float e0 = ex2f(fmaf(q0, kv, -m0));
        float e1 = ex2f(fmaf(q1, kv, -m1));
        d0 += e0;
        d1 += e1;
        n0 = fmaf(e0, vv, n0);
        n1 = fmaf(e1, vv, n1);
    }
    int i0 = b * Hd + tid, i1 = i0 + 256;
    float r0 = h[i0] + n0 / d0;
    float r1 = h[i1] + n1 / d1;
    h[i0] = r0; h[i1] = r1;
    __nv_bfloat16 h0b = __float2bfloat16(r0);
    __nv_bfloat16 h1b = __float2bfloat16(r1);
    oh[i0] = h0b; ol[i0] = __float2bfloat16(r0 - __bfloat162float(h0b));
    oh[i1] = h1b; ol[i1] = __float2bfloat16(r1 - __bfloat162float(h1b));
}

// ---------------- reg head ----------------
__global__ __launch_bounds__(256) void reg_kernel(const float* __restrict__ fea,
                                                  const float* __restrict__ reg_w,
                                                  const float* __restrict__ reg_b,
                                                  float* __restrict__ out) {
    const int warp = (blockIdx.x * blockDim.x + threadIdx.x) >> 5;
    const int lane = threadIdx.x & 31;
    if (warp >= Bsz) return;
    float s = 0.f;
#pragma unroll
    for (int p = lane; p < Pd; p += 32)
        s = fmaf(fea[warp * Pd + p], reg_w[p], s);
#pragma unroll
    for (int o = 16; o; o >>= 1) s += __shfl_xor_sync(0xffffffffu, s, o);
    if (lane == 0) out[warp] = s + reg_b[0];
}

// ---------------- launcher (single stream, R11 structure) ----------------
extern "C" void kernel_launch(void* const* d_in, const int* in_sizes, int n_in,
                              void* d_out, int out_size) {
    const float* x      = (const float*)d_in[0];
    const float* lin0_w = (const float*)d_in[1];
    const float* lin0_b = (const float*)d_in[2];
    const float* b1_qw = (const float*)d_in[3];  const float* b1_qb = (const float*)d_in[4];
    const float* b1_kw = (const float*)d_in[5];  const float* b1_kb = (const float*)d_in[6];
    const float* b1_vw = (const float*)d_in[7];  const float* b1_vb = (const float*)d_in[8];
    const float* b1_f1w = (const float*)d_in[9]; const float* b1_f1b = (const float*)d_in[10];
    const float* b2_qw = (const float*)d_in[11]; const float* b2_qb = (const float*)d_in[12];
    const float* b2_kw = (const float*)d_in[13]; const float* b2_kb = (const float*)d_in[14];
    const float* b2_vw = (const float*)d_in[15]; const float* b2_vb = (const float*)d_in[16];
    const float* b2_f1w = (const float*)d_in[17]; const float* b2_f1b = (const float*)d_in[18];
    const float* fea_w = (const float*)d_in[19]; const float* fea_b = (const float*)d_in[20];
    const float* reg_w = (const float*)d_in[21]; const float* reg_b = (const float*)d_in[22];

    float* out_scalar = (float*)d_out;           // [B]
    float* out_fea    = (float*)d_out + Bsz;     // [B, P]

    float *h0, *h1, *qb, *kb, *vb;
    __nv_bfloat16 *wh, *wl, *pAh, *pAl, *pBh, *pBl;
    cudaGetSymbolAddress((void**)&h0, g_h0);
    cudaGetSymbolAddress((void**)&h1, g_h1);
    cudaGetSymbolAddress((void**)&qb, g_q);
    cudaGetSymbolAddress((void**)&kb, g_k);
    cudaGetSymbolAddress((void**)&vb, g_v);
    cudaGetSymbolAddress((void**)&wh, g_wh);
    cudaGetSymbolAddress((void**)&wl, g_wl);
    cudaGetSymbolAddress((void**)&pAh, g_pAh);
    cudaGetSymbolAddress((void**)&pAl, g_pAl);
    cudaGetSymbolAddress((void**)&pBh, g_pBh);
    cudaGetSymbolAddress((void**)&pBl, g_pBl);

    // opt-in to 73.7KB dynamic smem (idempotent host calls, no allocation)
    cudaFuncSetAttribute(tgemm_kernel<0, 512>, cudaFuncAttributeMaxDynamicSharedMemorySize, SMEM_DBL);
    cudaFuncSetAttribute(tgemm_kernel<1, 256>, cudaFuncAttributeMaxDynamicSharedMemorySize, SMEM_DBL);
    cudaFuncSetAttribute(tgemm_kernel<2, 512>, cudaFuncAttributeMaxDynamicSharedMemorySize, SMEM_DBL);
    cudaFuncSetAttribute(tgemm_kernel<3, 512>, cudaFuncAttributeMaxDynamicSharedMemorySize, SMEM_DBL);

    // 0) convert all weights + x to bf16 hi/lo
    {
        ConvArgs a{};
        const float* srcs[NSEG] = {lin0_w, b1_qw, b1_kw, b1_vw, b1_f1w,
                                   b2_qw, b2_kw, b2_vw, b2_f1w, fea_w, x};
        const int offs[NSEG] = {OFF_LIN0, OFF_B1Q, OFF_B1K, OFF_B1V, OFF_B1F,
                                OFF_B2Q, OFF_B2K, OFF_B2V, OFF_B2F, OFF_FEA, OFF_X};
        const int ns[NSEG] = {Hd*INd, Hd*Hd, Hd*Hd, Hd*Hd, Hd*Hd,
                              Hd*Hd, Hd*Hd, Hd*Hd, Hd*Hd, Pd*Hd, Bsz*INd};
        for (int s = 0; s < NSEG; s++) { a.src[s] = srcs[s]; a.off[s] = offs[s]; a.n4[s] = ns[s] / 4; }
        conv_kernel<<<dim3(48, NSEG), 256>>>(a);
    }

    // 1) lin0: h0 = x @ lin0_w^T + b  (+ bf16 pair A)
    {
        TGemmArgs a{};
        a.a_hi = wh + OFF_X; a.a_lo = wl + OFF_X;
        a.w_hi[0] = wh + OFF_LIN0; a.w_lo[0] = wl + OFF_LIN0;
        a.bias[0] = lin0_b; a.C[0] = h0;
        a.o_hi = pAh; a.o_lo = pAl; a.N = Hd;
        tgemm_kernel<1, 256><<<dim3(8, 16, 1), 128, SMEM_DBL>>>(a);
    }

    // ---- block 1 ----
    {
        TGemmArgs a{};
        a.a_hi = pAh; a.a_lo = pAl;
        a.w_hi[0] = wh + OFF_B1Q; a.w_lo[0] = wl + OFF_B1Q;
        a.w_hi[1] = wh + OFF_B1K; a.w_lo[1] = wl + OFF_B1K;
        a.w_hi[2] = wh + OFF_B1V; a.w_lo[2] = wl + OFF_B1V;
        a.bias[0] = b1_qb; a.bias[1] = b1_kb; a.bias[2] = b1_vb;
        a.C[0] = qb; a.C[1] = kb; a.C[2] = vb; a.N = Hd;
        tgemm_kernel<0, 512><<<dim3(8, 16, 3), 128, SMEM_DBL>>>(a);
    }
    attn_kernel<<<Bsz, 256>>>(qb, kb, vb, h0, pAh, pAl);
    {
        TGemmArgs a{};
        a.a_hi = pAh; a.a_lo = pAl;
        a.w_hi[0] = wh + OFF_B1F; a.w_lo[0] = wl + OFF_B1F;
        a.bias[0] = b1_f1b; a.res = h0; a.C[0] = h1;
        a.o_hi = pBh; a.o_lo = pBl; a.N = Hd;
        tgemm_kernel<2, 512><<<dim3(8, 16, 1), 128, SMEM_DBL>>>(a);
    }

    // ---- block 2 ----
    {
        TGemmArgs a{};
        a.a_hi = pBh; a.a_lo = pBl;
        a.w_hi[0] = wh + OFF_B2Q; a.w_lo[0] = wl + OFF_B2Q;
        a.w_hi[1] = wh + OFF_B2K; a.w_lo[1] = wl + OFF_B2K;
        a.w_hi[2] = wh + OFF_B2V; a.w_lo[2] = wl + OFF_B2V;
        a.bias[0] = b2_qb; a.bias[1] = b2_kb; a.bias[2] = b2_vb;
        a.C[0] = qb; a.C[1] = kb; a.C[2] = vb; a.N = Hd;
        tgemm_kernel<0, 512><<<dim3(8, 16, 3), 128, SMEM_DBL>>>(a);
    }
    attn_kernel<<<Bsz, 256>>>(qb, kb, vb, h1, pBh, pBl);
    {
        TGemmArgs a{};
        a.a_hi = pBh; a.a_lo = pBl;
        a.w_hi[0] = wh + OFF_B2F; a.w_lo[0] = wl + OFF_B2F;
        a.bias[0] = b2_f1b; a.res = h1; a.C[0] = h0;
        a.o_hi = pAh; a.o_lo = pAl; a.N = Hd;
        tgemm_kernel<2, 512><<<dim3(8, 16, 1), 128, SMEM_DBL>>>(a);
    }

    // 4) fea -> d_out directly
    {
        TGemmArgs a{};
        a.a_hi = pAh; a.a_lo = pAl;
        a.w_hi[0] = wh + OFF_FEA; a.w_lo[0] = wl + OFF_FEA;
        a.bias[0] = fea_b; a.C[0] = out_fea; a.N = Pd;
        tgemm_kernel<3, 512><<<dim3(2, 16, 1), 128, SMEM_DBL>>>(a);
    }

    // 5) out[b] = fea·reg_w + reg_b
    reg_kernel<<<(Bsz * 32) / 256, 256>>>(out_fea, reg_w, reg_b, out_scalar);
}